// round 16
// baseline (speedup 1.0000x reference)
#include <cuda_runtime.h>
#include <cuda_fp16.h>
#include <mma.h>
#include <cstdint>
#include <cstddef>

using namespace nvcuda;

// ---------------------------------------------------------------------------
// Fixed shapes: N=100000, E=1600000, F 128 -> 128 -> 64
// ---------------------------------------------------------------------------
#define MAX_N 100000
#define MAX_E 1600000
#define SCAN_CHUNK 1024
#define MAX_CHUNKS ((MAX_N + SCAN_CHUNK - 1) / SCAN_CHUNK)   // 98

// Scratch (device BSS — no allocation inside kernel_launch)
__device__ __half g_half[(size_t)MAX_N * 128];   // x @ W1, fp16
__device__ __half p_half[(size_t)MAX_N * 64];    // fused spmm1+gemm2 out, fp16
__device__ __align__(16) __half w1_fp16[128 * 128];  // W1 pre-converted
__device__ __align__(16) __half w2_fp16[128 * 64];   // W2 pre-converted

__device__ int   deg_buf   [MAX_N];
__device__ int   row_ptr   [MAX_N + 1];
__device__ int   cursor    [MAX_N];
__device__ int   part_buf  [MAX_CHUNKS];
__device__ int2  edge_sorted[MAX_E];             // packed (src, w_bits)

// ---------------------------------------------------------------------------
// Threefry-2x32, key = (0, 42) — bit-exact replica of jax threefry2x32 core
// ---------------------------------------------------------------------------
__device__ __forceinline__ void threefry_0_42(uint32_t x0, uint32_t x1,
                                              uint32_t& o0, uint32_t& o1)
{
    const uint32_t k0 = 0u, k1 = 42u;
    const uint32_t k2 = k0 ^ k1 ^ 0x1BD11BDAu;
    x0 += k0; x1 += k1;
#define TF_R(r) { x0 += x1; x1 = (x1 << (r)) | (x1 >> (32 - (r))); x1 ^= x0; }
    TF_R(13) TF_R(15) TF_R(26) TF_R(6)   x0 += k1; x1 += k2 + 1u;
    TF_R(17) TF_R(29) TF_R(16) TF_R(24)  x0 += k2; x1 += k0 + 2u;
    TF_R(13) TF_R(15) TF_R(26) TF_R(6)   x0 += k0; x1 += k1 + 3u;
    TF_R(17) TF_R(29) TF_R(16) TF_R(24)  x0 += k1; x1 += k2 + 4u;
    TF_R(13) TF_R(15) TF_R(26) TF_R(6)   x0 += k2; x1 += k0 + 5u;
#undef TF_R
    o0 = x0; o1 = x1;
}

__device__ __forceinline__ bool drop_mask(uint32_t i)
{
    uint32_t o0, o1;
    threefry_0_42(0u, i, o0, o1);
    return ((o0 ^ o1) & 0x80000000u) != 0u;   // true = drop (XOR-fold)
}

// ===========================================================================
// Prep: W1, W2 fp32 -> fp16 global images (once per launch; tiny)
// ===========================================================================
__global__ void k_prep_w(const float* __restrict__ W1, const float* __restrict__ W2)
{
    const int i = blockIdx.x * blockDim.x + threadIdx.x;
    if (i < 128 * 128) w1_fp16[i] = __float2half_rn(W1[i]);
    if (i < 128 * 64)  w2_fp16[i] = __float2half_rn(W2[i]);
}

// ===========================================================================
// GEMM1 (wmma fp16): g_half[M,128] = x[M,128] @ W1[128,128]  (R14-certified)
// ===========================================================================
#define G1_LD  136
#define G1_B_OFF   (128 * G1_LD)
#define G1_SMEM_HALFS (2 * 128 * G1_LD)
#define G1_STAGE_OFF  (G1_SMEM_HALFS * 2)
#define G1_SMEM_BYTES (G1_SMEM_HALFS * 2 + 8 * 16 * 16 * 4)

__global__ void __launch_bounds__(256, 2)
gemm1_wmma(const float* __restrict__ x, int M)
{
    extern __shared__ __align__(16) char smem_raw[];
    __half* Ah = (__half*)smem_raw;
    __half* Bh = Ah + G1_B_OFF;
    float*  stage = (float*)(smem_raw + G1_STAGE_OFF);

    const int tid = threadIdx.x;
    const int wid = tid >> 5;
    const int lane = tid & 31;
    const int m0  = blockIdx.x * 128;
    const int warp_m = wid >> 2;
    const int warp_n = wid & 3;

    for (int i = tid; i < 128 * 32; i += 256) {
        const int row = i >> 5;
        const int c4  = (i & 31) * 4;
        int grow = m0 + row;
        if (grow > M - 1) grow = M - 1;
        const float4 v = __ldg((const float4*)(x + (size_t)grow * 128 + c4));
        const __half2 h0 = __floats2half2_rn(v.x, v.y);
        const __half2 h1 = __floats2half2_rn(v.z, v.w);
        *(__half2*)(Ah + row * G1_LD + c4)     = h0;
        *(__half2*)(Ah + row * G1_LD + c4 + 2) = h1;
    }
    for (int i = tid; i < 128 * 16; i += 256) {
        const int row = i >> 4;
        const int c8  = (i & 15) * 8;
        *(uint4*)(Bh + row * G1_LD + c8) =
            *(const uint4*)(w1_fp16 + row * 128 + c8);
    }
    __syncthreads();

    wmma::fragment<wmma::accumulator, 16, 16, 16, float> acc[4][2];
#pragma unroll
    for (int mf = 0; mf < 4; mf++)
#pragma unroll
        for (int nf = 0; nf < 2; nf++)
            wmma::fill_fragment(acc[mf][nf], 0.0f);

#pragma unroll
    for (int ks = 0; ks < 8; ks++) {
        wmma::fragment<wmma::matrix_b, 16, 16, 16, __half, wmma::row_major> bf[2];
#pragma unroll
        for (int nf = 0; nf < 2; nf++)
            wmma::load_matrix_sync(bf[nf],
                Bh + ks * 16 * G1_LD + warp_n * 32 + nf * 16, G1_LD);
#pragma unroll
        for (int mf = 0; mf < 4; mf++) {
            wmma::fragment<wmma::matrix_a, 16, 16, 16, __half, wmma::row_major> af;
            wmma::load_matrix_sync(af,
                Ah + (warp_m * 64 + mf * 16) * G1_LD + ks * 16, G1_LD);
#pragma unroll
            for (int nf = 0; nf < 2; nf++)
                wmma::mma_sync(acc[mf][nf], af, bf[nf], acc[mf][nf]);
        }
    }

    float* st = stage + wid * 256;
#pragma unroll
    for (int mf = 0; mf < 4; mf++) {
        const int r0 = m0 + warp_m * 64 + mf * 16;
        const bool valid = (r0 + 16 <= M);             // M % 16 == 0
#pragma unroll
        for (int nf = 0; nf < 2; nf++) {
            wmma::store_matrix_sync(st, acc[mf][nf], 16, wmma::mem_row_major);
            __syncwarp();
            if (valid) {
                const int row = lane >> 1;
                const int c0  = (lane & 1) * 8;
                const float* s = st + row * 16 + c0;
                uint4 o;
                __half2 q0 = __floats2half2_rn(s[0], s[1]);
                __half2 q1 = __floats2half2_rn(s[2], s[3]);
                __half2 q2 = __floats2half2_rn(s[4], s[5]);
                __half2 q3 = __floats2half2_rn(s[6], s[7]);
                o.x = *reinterpret_cast<const uint32_t*>(&q0);
                o.y = *reinterpret_cast<const uint32_t*>(&q1);
                o.z = *reinterpret_cast<const uint32_t*>(&q2);
                o.w = *reinterpret_cast<const uint32_t*>(&q3);
                *(uint4*)(g_half + (size_t)(r0 + row) * 128
                          + warp_n * 32 + nf * 16 + c0) = o;
            }
            __syncwarp();
        }
    }
}

// ===========================================================================
// FUSED SpMM1 + bias/relu/dropout + GEMM2 (wmma):
//   Phase 1: 8 warps x 16 dst rows — gather-accumulate spmm(A,g)[d],
//            epilogue -> fp16 h row parked in the SMEM A-tile (never global).
//   Phase 2: wmma gemm2 on the tile: p[tile] = h_tile @ W2  (fp16 out).
// Per-CTA W2 copy is fp16 (16 KB): 782 CTAs x 16 KB = 12.5 MB L2 — cheap.
// ===========================================================================
#define FG_LDA 136
#define FG_LDB 72
#define FG_A_HALFS (128 * FG_LDA)
#define FG_B_HALFS (128 * FG_LDB)
#define FG_STAGE_OFF ((FG_A_HALFS + FG_B_HALFS) * 2)
#define FG_SMEM_BYTES (FG_STAGE_OFF + 8 * 16 * 16 * 4)   // 53248 + 8192

__global__ void __launch_bounds__(256)
spmm1_gemm2_fused(const float* __restrict__ b1, int N)
{
    extern __shared__ __align__(16) char smem_raw[];
    __half* Ah = (__half*)smem_raw;                    // h tile [128][FG_LDA]
    __half* Bh = Ah + FG_A_HALFS;                      // W2     [128][FG_LDB]
    float*  stage = (float*)(smem_raw + FG_STAGE_OFF);

    const int tid = threadIdx.x;
    const int wid = tid >> 5;
    const int lane = tid & 31;
    const int m0  = blockIdx.x * 128;

    // Copy W2 fp16 image -> Bh (128 rows x 8 uint4)
    for (int i = tid; i < 128 * 8; i += 256) {
        const int row = i >> 3;
        const int c8  = (i & 7) * 8;
        *(uint4*)(Bh + row * FG_LDB + c8) =
            *(const uint4*)(w2_fp16 + row * 64 + c8);
    }

    // --- Phase 1: gather + epilogue, 16 rows per warp ---
    const float4 bv = *(const float4*)(b1 + lane * 4);
    const __half* __restrict__ G = g_half;

    for (int r = 0; r < 16; r++) {
        const int dl = wid * 16 + r;                   // local row 0..127
        const int d  = m0 + dl;
        if (d >= N) break;

        const int beg = row_ptr[d];
        const int end = row_ptr[d + 1];

        float4 acc = make_float4(0.f, 0.f, 0.f, 0.f);
        int j = beg;
        for (; j + 8 <= end; j += 8) {
            int2 e[8];
#pragma unroll
            for (int q = 0; q < 8; q++) e[q] = __ldg(&edge_sorted[j + q]);
            uint2 gv[8];
#pragma unroll
            for (int q = 0; q < 8; q++)
                gv[q] = *(const uint2*)(G + (size_t)e[q].x * 128 + lane * 4);
#pragma unroll
            for (int q = 0; q < 8; q++) {
                const float w = __int_as_float(e[q].y);
                const float2 f0 = __half22float2(*reinterpret_cast<const __half2*>(&gv[q].x));
                const float2 f1 = __half22float2(*reinterpret_cast<const __half2*>(&gv[q].y));
                acc.x += w * f0.x; acc.y += w * f0.y;
                acc.z += w * f1.x; acc.w += w * f1.y;
            }
        }
        for (; j < end; j++) {
            const int2 e = __ldg(&edge_sorted[j]);
            const float w = __int_as_float(e.y);
            const uint2 gv = *(const uint2*)(G + (size_t)e.x * 128 + lane * 4);
            const float2 f0 = __half22float2(*reinterpret_cast<const __half2*>(&gv.x));
            const float2 f1 = __half22float2(*reinterpret_cast<const __half2*>(&gv.y));
            acc.x += w * f0.x; acc.y += w * f0.y;
            acc.z += w * f1.x; acc.w += w * f1.y;
        }

        const uint32_t base = (uint32_t)d * 128u + (uint32_t)lane * 4u;
        float v0 = fmaxf(acc.x + bv.x, 0.f);
        float v1 = fmaxf(acc.y + bv.y, 0.f);
        float v2 = fmaxf(acc.z + bv.z, 0.f);
        float v3 = fmaxf(acc.w + bv.w, 0.f);
        v0 = drop_mask(base + 0u) ? 0.f : v0 * 2.f;
        v1 = drop_mask(base + 1u) ? 0.f : v1 * 2.f;
        v2 = drop_mask(base + 2u) ? 0.f : v2 * 2.f;
        v3 = drop_mask(base + 3u) ? 0.f : v3 * 2.f;

        uint2 o;
        const __half2 h0 = __floats2half2_rn(v0, v1);
        const __half2 h1 = __floats2half2_rn(v2, v3);
        o.x = *reinterpret_cast<const uint32_t*>(&h0);
        o.y = *reinterpret_cast<const uint32_t*>(&h1);
        *(uint2*)(Ah + dl * FG_LDA + lane * 4) = o;
    }
    __syncthreads();

    // --- Phase 2: wmma gemm2 on the SMEM tile (R15-certified layout) ---
    const int warp_m = wid >> 1;   // 0..3
    const int warp_n = wid & 1;    // 0..1

    wmma::fragment<wmma::accumulator, 16, 16, 16, float> acc2[2][2];
#pragma unroll
    for (int mf = 0; mf < 2; mf++)
#pragma unroll
        for (int nf = 0; nf < 2; nf++)
            wmma::fill_fragment(acc2[mf][nf], 0.0f);

#pragma unroll
    for (int ks = 0; ks < 8; ks++) {
        wmma::fragment<wmma::matrix_b, 16, 16, 16, __half, wmma::row_major> bf[2];
#pragma unroll
        for (int nf = 0; nf < 2; nf++)
            wmma::load_matrix_sync(bf[nf],
                Bh + ks * 16 * FG_LDB + warp_n * 32 + nf * 16, FG_LDB);
#pragma unroll
        for (int mf = 0; mf < 2; mf++) {
            wmma::fragment<wmma::matrix_a, 16, 16, 16, __half, wmma::row_major> af;
            wmma::load_matrix_sync(af,
                Ah + (warp_m * 32 + mf * 16) * FG_LDA + ks * 16, FG_LDA);
#pragma unroll
            for (int nf = 0; nf < 2; nf++)
                wmma::mma_sync(acc2[mf][nf], af, bf[nf], acc2[mf][nf]);
        }
    }

    float* st = stage + wid * 256;
#pragma unroll
    for (int mf = 0; mf < 2; mf++) {
        const int r0 = m0 + warp_m * 32 + mf * 16;
        const bool valid = (r0 + 16 <= N);             // N % 16 == 0
#pragma unroll
        for (int nf = 0; nf < 2; nf++) {
            wmma::store_matrix_sync(st, acc2[mf][nf], 16, wmma::mem_row_major);
            __syncwarp();
            if (valid) {
                const int row = lane >> 1;
                const int c0  = (lane & 1) * 8;
                const float* s = st + row * 16 + c0;
                uint4 o;
                __half2 q0 = __floats2half2_rn(s[0], s[1]);
                __half2 q1 = __floats2half2_rn(s[2], s[3]);
                __half2 q2 = __floats2half2_rn(s[4], s[5]);
                __half2 q3 = __floats2half2_rn(s[6], s[7]);
                o.x = *reinterpret_cast<const uint32_t*>(&q0);
                o.y = *reinterpret_cast<const uint32_t*>(&q1);
                o.z = *reinterpret_cast<const uint32_t*>(&q2);
                o.w = *reinterpret_cast<const uint32_t*>(&q3);
                *(uint4*)(p_half + (size_t)(r0 + row) * 64
                          + warp_n * 32 + nf * 16 + c0) = o;
            }
            __syncwarp();
        }
    }
}

// ===========================================================================
// CSR build: deg -> part sums -> shuffle scan(+inline offset) -> scatter
// ===========================================================================
__global__ void k_zero_deg(int N)
{
    const int i = blockIdx.x * blockDim.x + threadIdx.x;
    if (i < N) deg_buf[i] = 0;
}

__global__ void k_hist(const int* __restrict__ dst, int E)
{
    const int e = blockIdx.x * blockDim.x + threadIdx.x;
    if (e < E) atomicAdd(&deg_buf[dst[e]], 1);
}

__global__ void k_part_sums(int N)
{
    __shared__ int sm[256];
    const int b = blockIdx.x, t = threadIdx.x;
    int s = 0;
#pragma unroll
    for (int k = 0; k < 4; k++) {
        const int i = b * SCAN_CHUNK + k * 256 + t;
        if (i < N) s += deg_buf[i];
    }
    sm[t] = s; __syncthreads();
    for (int off = 128; off > 0; off >>= 1) {
        if (t < off) sm[t] += sm[t + off];
        __syncthreads();
    }
    if (t == 0) part_buf[b] = sm[0];
}

// Shuffle-based chunk scan (3 barriers) with inline global-offset reduce.
__global__ void k_scan_chunks(int N, int E)
{
    __shared__ int warp_sums[32];
    __shared__ int chunk_off;
    const int b = blockIdx.x, t = threadIdx.x;
    const int warp = t >> 5, lane = t & 31;
    const int i = b * SCAN_CHUNK + t;
    const int v = (i < N) ? deg_buf[i] : 0;

    // inclusive intra-warp scan
    int s = v;
#pragma unroll
    for (int off = 1; off < 32; off <<= 1) {
        const int y = __shfl_up_sync(0xffffffffu, s, off);
        if (lane >= off) s += y;
    }
    if (lane == 31) warp_sums[warp] = s;

    // warp 0: global offset = sum part_buf[0..b-1]  (MAX_CHUNKS <= 128)
    if (warp == 0) {
        int o = 0;
        for (int k = lane; k < b; k += 32) o += part_buf[k];
#pragma unroll
        for (int off = 16; off > 0; off >>= 1)
            o += __shfl_down_sync(0xffffffffu, o, off);
        if (lane == 0) chunk_off = o;
    }
    __syncthreads();

    // warp 1: exclusive scan of 32 warp sums
    if (warp == 1) {
        const int ws = warp_sums[lane];
        int sc = ws;
#pragma unroll
        for (int off = 1; off < 32; off <<= 1) {
            const int y = __shfl_up_sync(0xffffffffu, sc, off);
            if (lane >= off) sc += y;
        }
        warp_sums[lane] = sc - ws;   // exclusive
    }
    __syncthreads();

    if (i < N) {
        const int ex = (s - v) + warp_sums[warp] + chunk_off;
        row_ptr[i] = ex;
        cursor[i]  = ex;
    }
    if (b == 0 && t == 0) row_ptr[N] = E;
}

__global__ void k_scatter(const int* __restrict__ src, const int* __restrict__ dst,
                          const float* __restrict__ ew, int E)
{
    const int e = blockIdx.x * blockDim.x + threadIdx.x;
    if (e >= E) return;
    const int pos = atomicAdd(&cursor[dst[e]], 1);
    int2 pkt;
    pkt.x = src[e];
    pkt.y = __float_as_int(ew[e]);
    edge_sorted[pos] = pkt;
}

// ===========================================================================
// SpMM2 (CSR, F=64, fp16 gather) fused with +b2. Lane owns 2 features.
// ===========================================================================
__global__ void __launch_bounds__(256)
spmm2_fused(const float* __restrict__ b2, float* __restrict__ out, int N)
{
    const int d    = (blockIdx.x * blockDim.x + threadIdx.x) >> 5;
    const int lane = threadIdx.x & 31;
    if (d >= N) return;

    const int beg = row_ptr[d];
    const int end = row_ptr[d + 1];

    float2 acc = make_float2(0.f, 0.f);
    const __half* __restrict__ P = p_half;

    int j = beg;
    for (; j + 8 <= end; j += 8) {
        int2 e[8];
#pragma unroll
        for (int q = 0; q < 8; q++) e[q] = __ldg(&edge_sorted[j + q]);
        __half2 pv[8];
#pragma unroll
        for (int q = 0; q < 8; q++)
            pv[q] = *(const __half2*)(P + (size_t)e[q].x * 64 + lane * 2);
#pragma unroll
        for (int q = 0; q < 8; q++) {
            const float w = __int_as_float(e[q].y);
            const float2 f = __half22float2(pv[q]);
            acc.x += w * f.x; acc.y += w * f.y;
        }
    }
    for (; j < end; j++) {
        const int2 e = __ldg(&edge_sorted[j]);
        const float w = __int_as_float(e.y);
        const float2 f = __half22float2(*(const __half2*)(P + (size_t)e.x * 64 + lane * 2));
        acc.x += w * f.x; acc.y += w * f.y;
    }

    const float2 bv = *(const float2*)(b2 + lane * 2);
    float2 o; o.x = acc.x + bv.x; o.y = acc.y + bv.y;
    *(float2*)(out + (size_t)d * 64 + lane * 2) = o;
}

// ---------------------------------------------------------------------------
// kernel_launch
// inputs: x, edge_weight, W1, b1, W2, b2, src, dst, n_nodes
// Fork: main = prep + gemm1 (wmma), s2 = CSR build. Join before fused kernel.
// ---------------------------------------------------------------------------
extern "C" void kernel_launch(void* const* d_in, const int* in_sizes, int n_in,
                              void* d_out, int out_size)
{
    const float* x   = (const float*)d_in[0];
    const float* ew  = (const float*)d_in[1];
    const float* W1  = (const float*)d_in[2];
    const float* b1  = (const float*)d_in[3];
    const float* W2  = (const float*)d_in[4];
    const float* b2  = (const float*)d_in[5];
    const int*   src = (const int*)d_in[6];
    const int*   dst = (const int*)d_in[7];

    const int N = in_sizes[0] / 128;
    const int E = in_sizes[1];
    float* out = (float*)d_out;

    const int nchunks = (N + SCAN_CHUNK - 1) / SCAN_CHUNK;

    static cudaStream_t s2 = nullptr;
    static cudaEvent_t  ev_fork = nullptr, ev_join = nullptr;
    static bool tried = false;
    if (!tried) {
        tried = true;
        cudaFuncSetAttribute(gemm1_wmma, cudaFuncAttributeMaxDynamicSharedMemorySize,
                             G1_SMEM_BYTES);
        cudaFuncSetAttribute(spmm1_gemm2_fused, cudaFuncAttributeMaxDynamicSharedMemorySize,
                             FG_SMEM_BYTES);
        if (cudaStreamCreateWithFlags(&s2, cudaStreamNonBlocking) != cudaSuccess) s2 = nullptr;
        if (s2) {
            cudaEventCreateWithFlags(&ev_fork, cudaEventDisableTiming);
            cudaEventCreateWithFlags(&ev_join, cudaEventDisableTiming);
        }
    }

    cudaStream_t cs = s2 ? s2 : (cudaStream_t)0;

    if (s2) {
        cudaEventRecord(ev_fork, 0);
        cudaStreamWaitEvent(s2, ev_fork, 0);
    }

    // --- CSR build on secondary stream (independent of gemm1) ---
    k_zero_deg   <<<(N + 255) / 256, 256, 0, cs>>>(N);
    k_hist       <<<(E + 255) / 256, 256, 0, cs>>>(dst, E);
    k_part_sums  <<<nchunks, 256, 0, cs>>>(N);
    k_scan_chunks<<<nchunks, SCAN_CHUNK, 0, cs>>>(N, E);
    k_scatter    <<<(E + 255) / 256, 256, 0, cs>>>(src, dst, ew, E);

    if (s2) cudaEventRecord(ev_join, s2);

    // --- main stream: W1+W2 fp16 prep + tensor-core gemm1 ---
    k_prep_w<<<(128 * 128 + 255) / 256, 256>>>(W1, W2);
    gemm1_wmma<<<(N + 127) / 128, 256, G1_SMEM_BYTES>>>(x, N);

    if (s2) cudaStreamWaitEvent((cudaStream_t)0, ev_join, 0);

    // p = (relu(spmm(A,g)+b1)*mask*2) @ W2   — fused, h never leaves SMEM
    spmm1_gemm2_fused<<<(N + 127) / 128, 256, FG_SMEM_BYTES>>>(b1, N);
    // out = spmm(A, p) + b2
    spmm2_fused<<<(N * 32 + 255) / 256, 256>>>(b2, out, N);
}

// round 17
// speedup vs baseline: 1.0407x; 1.0407x over previous
#include <cuda_runtime.h>
#include <cuda_fp16.h>
#include <mma.h>
#include <cstdint>
#include <cstddef>

using namespace nvcuda;

// ---------------------------------------------------------------------------
// Fixed shapes: N=100000, E=1600000, F 128 -> 128 -> 64
// ---------------------------------------------------------------------------
#define MAX_N 100000
#define MAX_E 1600000
#define SCAN_CHUNK 1024
#define MAX_CHUNKS ((MAX_N + SCAN_CHUNK - 1) / SCAN_CHUNK)   // 98

// Scratch (device BSS — no allocation inside kernel_launch)
__device__ __half g_half[(size_t)MAX_N * 128];   // x @ W1, fp16
__device__ __half h_half[(size_t)MAX_N * 128];   // relu+bias+dropout, fp16
__device__ __half p_half[(size_t)MAX_N * 64];    // h @ W2, fp16
__device__ __align__(16) __half w1_fp16[128 * 128];
__device__ __align__(16) __half w2_fp16[128 * 64];

__device__ int   deg_buf   [MAX_N];
__device__ int   row_ptr   [MAX_N + 1];
__device__ int   cursor    [MAX_N];
__device__ int   part_buf  [MAX_CHUNKS];
__device__ int2  edge_sorted[MAX_E];             // packed (src, w_bits)

// ---------------------------------------------------------------------------
// Threefry-2x32, key = (0, 42) — bit-exact replica of jax threefry2x32 core
// ---------------------------------------------------------------------------
__device__ __forceinline__ void threefry_0_42(uint32_t x0, uint32_t x1,
                                              uint32_t& o0, uint32_t& o1)
{
    const uint32_t k0 = 0u, k1 = 42u;
    const uint32_t k2 = k0 ^ k1 ^ 0x1BD11BDAu;
    x0 += k0; x1 += k1;
#define TF_R(r) { x0 += x1; x1 = (x1 << (r)) | (x1 >> (32 - (r))); x1 ^= x0; }
    TF_R(13) TF_R(15) TF_R(26) TF_R(6)   x0 += k1; x1 += k2 + 1u;
    TF_R(17) TF_R(29) TF_R(16) TF_R(24)  x0 += k2; x1 += k0 + 2u;
    TF_R(13) TF_R(15) TF_R(26) TF_R(6)   x0 += k0; x1 += k1 + 3u;
    TF_R(17) TF_R(29) TF_R(16) TF_R(24)  x0 += k1; x1 += k2 + 4u;
    TF_R(13) TF_R(15) TF_R(26) TF_R(6)   x0 += k2; x1 += k0 + 5u;
#undef TF_R
    o0 = x0; o1 = x1;
}

__device__ __forceinline__ bool drop_mask(uint32_t i)
{
    uint32_t o0, o1;
    threefry_0_42(0u, i, o0, o1);
    return ((o0 ^ o1) & 0x80000000u) != 0u;   // true = drop (XOR-fold)
}

// ===========================================================================
// Prep: W1, W2 fp32 -> fp16 global images (once per launch; tiny)
// ===========================================================================
__global__ void k_prep_w(const float* __restrict__ W1, const float* __restrict__ W2)
{
    const int i = blockIdx.x * blockDim.x + threadIdx.x;
    if (i < 128 * 128) w1_fp16[i] = __float2half_rn(W1[i]);
    if (i < 128 * 64)  w2_fp16[i] = __float2half_rn(W2[i]);
}

// ===========================================================================
// GEMM1 (wmma fp16): g_half[M,128] = x[M,128] @ W1[128,128]  (R14-certified)
// ===========================================================================
#define G1_LD  136
#define G1_B_OFF   (128 * G1_LD)
#define G1_SMEM_HALFS (2 * 128 * G1_LD)
#define G1_STAGE_OFF  (G1_SMEM_HALFS * 2)
#define G1_SMEM_BYTES (G1_SMEM_HALFS * 2 + 8 * 16 * 16 * 4)

__global__ void __launch_bounds__(256, 2)
gemm1_wmma(const float* __restrict__ x, int M)
{
    extern __shared__ __align__(16) char smem_raw[];
    __half* Ah = (__half*)smem_raw;
    __half* Bh = Ah + G1_B_OFF;
    float*  stage = (float*)(smem_raw + G1_STAGE_OFF);

    const int tid = threadIdx.x;
    const int wid = tid >> 5;
    const int lane = tid & 31;
    const int m0  = blockIdx.x * 128;
    const int warp_m = wid >> 2;
    const int warp_n = wid & 3;

    for (int i = tid; i < 128 * 32; i += 256) {
        const int row = i >> 5;
        const int c4  = (i & 31) * 4;
        int grow = m0 + row;
        if (grow > M - 1) grow = M - 1;
        const float4 v = __ldg((const float4*)(x + (size_t)grow * 128 + c4));
        const __half2 h0 = __floats2half2_rn(v.x, v.y);
        const __half2 h1 = __floats2half2_rn(v.z, v.w);
        *(__half2*)(Ah + row * G1_LD + c4)     = h0;
        *(__half2*)(Ah + row * G1_LD + c4 + 2) = h1;
    }
    for (int i = tid; i < 128 * 16; i += 256) {
        const int row = i >> 4;
        const int c8  = (i & 15) * 8;
        *(uint4*)(Bh + row * G1_LD + c8) =
            *(const uint4*)(w1_fp16 + row * 128 + c8);
    }
    __syncthreads();

    wmma::fragment<wmma::accumulator, 16, 16, 16, float> acc[4][2];
#pragma unroll
    for (int mf = 0; mf < 4; mf++)
#pragma unroll
        for (int nf = 0; nf < 2; nf++)
            wmma::fill_fragment(acc[mf][nf], 0.0f);

#pragma unroll
    for (int ks = 0; ks < 8; ks++) {
        wmma::fragment<wmma::matrix_b, 16, 16, 16, __half, wmma::row_major> bf[2];
#pragma unroll
        for (int nf = 0; nf < 2; nf++)
            wmma::load_matrix_sync(bf[nf],
                Bh + ks * 16 * G1_LD + warp_n * 32 + nf * 16, G1_LD);
#pragma unroll
        for (int mf = 0; mf < 4; mf++) {
            wmma::fragment<wmma::matrix_a, 16, 16, 16, __half, wmma::row_major> af;
            wmma::load_matrix_sync(af,
                Ah + (warp_m * 64 + mf * 16) * G1_LD + ks * 16, G1_LD);
#pragma unroll
            for (int nf = 0; nf < 2; nf++)
                wmma::mma_sync(acc[mf][nf], af, bf[nf], acc[mf][nf]);
        }
    }

    float* st = stage + wid * 256;
#pragma unroll
    for (int mf = 0; mf < 4; mf++) {
        const int r0 = m0 + warp_m * 64 + mf * 16;
        const bool valid = (r0 + 16 <= M);             // M % 16 == 0
#pragma unroll
        for (int nf = 0; nf < 2; nf++) {
            wmma::store_matrix_sync(st, acc[mf][nf], 16, wmma::mem_row_major);
            __syncwarp();
            if (valid) {
                const int row = lane >> 1;
                const int c0  = (lane & 1) * 8;
                const float* s = st + row * 16 + c0;
                uint4 o;
                __half2 q0 = __floats2half2_rn(s[0], s[1]);
                __half2 q1 = __floats2half2_rn(s[2], s[3]);
                __half2 q2 = __floats2half2_rn(s[4], s[5]);
                __half2 q3 = __floats2half2_rn(s[6], s[7]);
                o.x = *reinterpret_cast<const uint32_t*>(&q0);
                o.y = *reinterpret_cast<const uint32_t*>(&q1);
                o.z = *reinterpret_cast<const uint32_t*>(&q2);
                o.w = *reinterpret_cast<const uint32_t*>(&q3);
                *(uint4*)(g_half + (size_t)(r0 + row) * 128
                          + warp_n * 32 + nf * 16 + c0) = o;
            }
            __syncwarp();
        }
    }
}

// ===========================================================================
// GEMM2 (wmma fp16): p_half[m_base+.., 64] = h_half @ W2  (R15-certified)
// m_base parameter supports half-split pipelining.
// ===========================================================================
#define G2_LDA 136
#define G2_LDB 72
#define G2_A_HALFS (128 * G2_LDA)
#define G2_B_HALFS (128 * G2_LDB)
#define G2_STAGE_OFF ((G2_A_HALFS + G2_B_HALFS) * 2)
#define G2_SMEM_BYTES (G2_STAGE_OFF + 8 * 16 * 16 * 4)

__global__ void __launch_bounds__(256, 2)
gemm2_wmma(int m_base, int M)
{
    extern __shared__ __align__(16) char smem_raw[];
    __half* Ah = (__half*)smem_raw;
    __half* Bh = Ah + G2_A_HALFS;
    float*  stage = (float*)(smem_raw + G2_STAGE_OFF);

    const int tid = threadIdx.x;
    const int wid = tid >> 5;
    const int lane = tid & 31;
    const int m0  = m_base + blockIdx.x * 128;
    const int warp_m = wid >> 1;
    const int warp_n = wid & 1;

    for (int i = tid; i < 128 * 16; i += 256) {
        const int row = i >> 4;
        const int c8  = (i & 15) * 8;
        int grow = m0 + row;
        if (grow > M - 1) grow = M - 1;
        *(uint4*)(Ah + row * G2_LDA + c8) =
            *(const uint4*)(h_half + (size_t)grow * 128 + c8);
    }
    for (int i = tid; i < 128 * 8; i += 256) {
        const int row = i >> 3;
        const int c8  = (i & 7) * 8;
        *(uint4*)(Bh + row * G2_LDB + c8) =
            *(const uint4*)(w2_fp16 + row * 64 + c8);
    }
    __syncthreads();

    wmma::fragment<wmma::accumulator, 16, 16, 16, float> acc[2][2];
#pragma unroll
    for (int mf = 0; mf < 2; mf++)
#pragma unroll
        for (int nf = 0; nf < 2; nf++)
            wmma::fill_fragment(acc[mf][nf], 0.0f);

#pragma unroll
    for (int ks = 0; ks < 8; ks++) {
        wmma::fragment<wmma::matrix_b, 16, 16, 16, __half, wmma::row_major> bf[2];
#pragma unroll
        for (int nf = 0; nf < 2; nf++)
            wmma::load_matrix_sync(bf[nf],
                Bh + ks * 16 * G2_LDB + warp_n * 32 + nf * 16, G2_LDB);
#pragma unroll
        for (int mf = 0; mf < 2; mf++) {
            wmma::fragment<wmma::matrix_a, 16, 16, 16, __half, wmma::row_major> af;
            wmma::load_matrix_sync(af,
                Ah + (warp_m * 32 + mf * 16) * G2_LDA + ks * 16, G2_LDA);
#pragma unroll
            for (int nf = 0; nf < 2; nf++)
                wmma::mma_sync(acc[mf][nf], af, bf[nf], acc[mf][nf]);
        }
    }

    float* st = stage + wid * 256;
#pragma unroll
    for (int mf = 0; mf < 2; mf++) {
        const int r0 = m0 + warp_m * 32 + mf * 16;
        const bool valid = (r0 + 16 <= M);             // M % 16 == 0
#pragma unroll
        for (int nf = 0; nf < 2; nf++) {
            wmma::store_matrix_sync(st, acc[mf][nf], 16, wmma::mem_row_major);
            __syncwarp();
            if (valid) {
                const int row = lane >> 1;
                const int c0  = (lane & 1) * 8;
                const float* s = st + row * 16 + c0;
                uint4 o;
                __half2 q0 = __floats2half2_rn(s[0], s[1]);
                __half2 q1 = __floats2half2_rn(s[2], s[3]);
                __half2 q2 = __floats2half2_rn(s[4], s[5]);
                __half2 q3 = __floats2half2_rn(s[6], s[7]);
                o.x = *reinterpret_cast<const uint32_t*>(&q0);
                o.y = *reinterpret_cast<const uint32_t*>(&q1);
                o.z = *reinterpret_cast<const uint32_t*>(&q2);
                o.w = *reinterpret_cast<const uint32_t*>(&q3);
                *(uint4*)(p_half + (size_t)(r0 + row) * 64
                          + warp_n * 32 + nf * 16 + c0) = o;
            }
            __syncwarp();
        }
    }
}

// ===========================================================================
// CSR build: deg -> part sums -> shuffle scan(+inline offset) -> scatter
// ===========================================================================
__global__ void k_zero_deg(int N)
{
    const int i = blockIdx.x * blockDim.x + threadIdx.x;
    if (i < N) deg_buf[i] = 0;
}

__global__ void k_hist(const int* __restrict__ dst, int E)
{
    const int e = blockIdx.x * blockDim.x + threadIdx.x;
    if (e < E) atomicAdd(&deg_buf[dst[e]], 1);
}

__global__ void k_part_sums(int N)
{
    __shared__ int sm[256];
    const int b = blockIdx.x, t = threadIdx.x;
    int s = 0;
#pragma unroll
    for (int k = 0; k < 4; k++) {
        const int i = b * SCAN_CHUNK + k * 256 + t;
        if (i < N) s += deg_buf[i];
    }
    sm[t] = s; __syncthreads();
    for (int off = 128; off > 0; off >>= 1) {
        if (t < off) sm[t] += sm[t + off];
        __syncthreads();
    }
    if (t == 0) part_buf[b] = sm[0];
}

// Shuffle-based chunk scan (3 barriers) with inline global-offset reduce.
__global__ void k_scan_chunks(int N, int E)
{
    __shared__ int warp_sums[32];
    __shared__ int chunk_off;
    const int b = blockIdx.x, t = threadIdx.x;
    const int warp = t >> 5, lane = t & 31;
    const int i = b * SCAN_CHUNK + t;
    const int v = (i < N) ? deg_buf[i] : 0;

    int s = v;
#pragma unroll
    for (int off = 1; off < 32; off <<= 1) {
        const int y = __shfl_up_sync(0xffffffffu, s, off);
        if (lane >= off) s += y;
    }
    if (lane == 31) warp_sums[warp] = s;

    if (warp == 0) {
        int o = 0;
        for (int k = lane; k < b; k += 32) o += part_buf[k];
#pragma unroll
        for (int off = 16; off > 0; off >>= 1)
            o += __shfl_down_sync(0xffffffffu, o, off);
        if (lane == 0) chunk_off = o;
    }
    __syncthreads();

    if (warp == 1) {
        const int ws = warp_sums[lane];
        int sc = ws;
#pragma unroll
        for (int off = 1; off < 32; off <<= 1) {
            const int y = __shfl_up_sync(0xffffffffu, sc, off);
            if (lane >= off) sc += y;
        }
        warp_sums[lane] = sc - ws;
    }
    __syncthreads();

    if (i < N) {
        const int ex = (s - v) + warp_sums[warp] + chunk_off;
        row_ptr[i] = ex;
        cursor[i]  = ex;
    }
    if (b == 0 && t == 0) row_ptr[N] = E;
}

__global__ void k_scatter(const int* __restrict__ src, const int* __restrict__ dst,
                          const float* __restrict__ ew, int E)
{
    const int e = blockIdx.x * blockDim.x + threadIdx.x;
    if (e >= E) return;
    const int pos = atomicAdd(&cursor[dst[e]], 1);
    int2 pkt;
    pkt.x = src[e];
    pkt.y = __float_as_int(ew[e]);
    edge_sorted[pos] = pkt;
}

// ===========================================================================
// SpMM1 (CSR, F=128, fp16 gather) + bias/relu/dropout (fp16 out).
// d_base supports half-split pipelining. Standalone — high occupancy (R16
// post-mortem: fused 3-CTA/SM variant starved gather MLP).
// ===========================================================================
__global__ void __launch_bounds__(256)
spmm1_fused(const float* __restrict__ b1, int d_base, int d_end)
{
    const int d    = d_base + ((blockIdx.x * blockDim.x + threadIdx.x) >> 5);
    const int lane = threadIdx.x & 31;
    if (d >= d_end) return;

    const int beg = row_ptr[d];
    const int end = row_ptr[d + 1];

    float4 acc = make_float4(0.f, 0.f, 0.f, 0.f);
    const __half* __restrict__ G = g_half;

    int j = beg;
    for (; j + 8 <= end; j += 8) {
        int2 e[8];
#pragma unroll
        for (int q = 0; q < 8; q++) e[q] = __ldg(&edge_sorted[j + q]);
        uint2 gv[8];
#pragma unroll
        for (int q = 0; q < 8; q++)
            gv[q] = *(const uint2*)(G + (size_t)e[q].x * 128 + lane * 4);
#pragma unroll
        for (int q = 0; q < 8; q++) {
            const float w = __int_as_float(e[q].y);
            const float2 f0 = __half22float2(*reinterpret_cast<const __half2*>(&gv[q].x));
            const float2 f1 = __half22float2(*reinterpret_cast<const __half2*>(&gv[q].y));
            acc.x += w * f0.x; acc.y += w * f0.y;
            acc.z += w * f1.x; acc.w += w * f1.y;
        }
    }
    for (; j < end; j++) {
        const int2 e = __ldg(&edge_sorted[j]);
        const float w = __int_as_float(e.y);
        const uint2 gv = *(const uint2*)(G + (size_t)e.x * 128 + lane * 4);
        const float2 f0 = __half22float2(*reinterpret_cast<const __half2*>(&gv.x));
        const float2 f1 = __half22float2(*reinterpret_cast<const __half2*>(&gv.y));
        acc.x += w * f0.x; acc.y += w * f0.y;
        acc.z += w * f1.x; acc.w += w * f1.y;
    }

    const float4 bv = *(const float4*)(b1 + lane * 4);
    const uint32_t base = (uint32_t)d * 128u + (uint32_t)lane * 4u;

    float v0 = fmaxf(acc.x + bv.x, 0.f);
    float v1 = fmaxf(acc.y + bv.y, 0.f);
    float v2 = fmaxf(acc.z + bv.z, 0.f);
    float v3 = fmaxf(acc.w + bv.w, 0.f);
    v0 = drop_mask(base + 0u) ? 0.f : v0 * 2.f;
    v1 = drop_mask(base + 1u) ? 0.f : v1 * 2.f;
    v2 = drop_mask(base + 2u) ? 0.f : v2 * 2.f;
    v3 = drop_mask(base + 3u) ? 0.f : v3 * 2.f;

    uint2 o;
    const __half2 h0 = __floats2half2_rn(v0, v1);
    const __half2 h1 = __floats2half2_rn(v2, v3);
    o.x = *reinterpret_cast<const uint32_t*>(&h0);
    o.y = *reinterpret_cast<const uint32_t*>(&h1);
    *(uint2*)(h_half + (size_t)d * 128 + lane * 4) = o;
}

// ===========================================================================
// SpMM2 (CSR, F=64, fp16 gather) fused with +b2. Lane owns 2 features.
// ===========================================================================
__global__ void __launch_bounds__(256)
spmm2_fused(const float* __restrict__ b2, float* __restrict__ out, int N)
{
    const int d    = (blockIdx.x * blockDim.x + threadIdx.x) >> 5;
    const int lane = threadIdx.x & 31;
    if (d >= N) return;

    const int beg = row_ptr[d];
    const int end = row_ptr[d + 1];

    float2 acc = make_float2(0.f, 0.f);
    const __half* __restrict__ P = p_half;

    int j = beg;
    for (; j + 8 <= end; j += 8) {
        int2 e[8];
#pragma unroll
        for (int q = 0; q < 8; q++) e[q] = __ldg(&edge_sorted[j + q]);
        __half2 pv[8];
#pragma unroll
        for (int q = 0; q < 8; q++)
            pv[q] = *(const __half2*)(P + (size_t)e[q].x * 64 + lane * 2);
#pragma unroll
        for (int q = 0; q < 8; q++) {
            const float w = __int_as_float(e[q].y);
            const float2 f = __half22float2(pv[q]);
            acc.x += w * f.x; acc.y += w * f.y;
        }
    }
    for (; j < end; j++) {
        const int2 e = __ldg(&edge_sorted[j]);
        const float w = __int_as_float(e.y);
        const float2 f = __half22float2(*(const __half2*)(P + (size_t)e.x * 64 + lane * 2));
        acc.x += w * f.x; acc.y += w * f.y;
    }

    const float2 bv = *(const float2*)(b2 + lane * 2);
    float2 o; o.x = acc.x + bv.x; o.y = acc.y + bv.y;
    *(float2*)(out + (size_t)d * 64 + lane * 2) = o;
}

// ---------------------------------------------------------------------------
// kernel_launch
// inputs: x, edge_weight, W1, b1, W2, b2, src, dst, n_nodes
// Pipeline: fork(CSR || prep+gemm1) -> spmm1_h0 -> [s2: gemm2_h0] || spmm1_h1
//           -> gemm2_h1 -> join(gemm2_h0) -> spmm2
// ---------------------------------------------------------------------------
extern "C" void kernel_launch(void* const* d_in, const int* in_sizes, int n_in,
                              void* d_out, int out_size)
{
    const float* x   = (const float*)d_in[0];
    const float* ew  = (const float*)d_in[1];
    const float* W1  = (const float*)d_in[2];
    const float* b1  = (const float*)d_in[3];
    const float* W2  = (const float*)d_in[4];
    const float* b2  = (const float*)d_in[5];
    const int*   src = (const int*)d_in[6];
    const int*   dst = (const int*)d_in[7];

    const int N = in_sizes[0] / 128;
    const int E = in_sizes[1];
    float* out = (float*)d_out;

    const int nchunks = (N + SCAN_CHUNK - 1) / SCAN_CHUNK;
    const int nblk    = (N + 127) / 128;          // 128-row tiles
    const int nblk_h0 = nblk / 2;                 // first half (full tiles)
    const int NH      = nblk_h0 * 128;            // rows in half 0
    const int nblk_h1 = nblk - nblk_h0;

    static cudaStream_t s2 = nullptr;
    static cudaEvent_t  ev_fork = nullptr, ev_join = nullptr;
    static cudaEvent_t  ev_sp1h0 = nullptr, ev_g2h0 = nullptr;
    static bool tried = false;
    if (!tried) {
        tried = true;
        cudaFuncSetAttribute(gemm1_wmma, cudaFuncAttributeMaxDynamicSharedMemorySize,
                             G1_SMEM_BYTES);
        cudaFuncSetAttribute(gemm2_wmma, cudaFuncAttributeMaxDynamicSharedMemorySize,
                             G2_SMEM_BYTES);
        if (cudaStreamCreateWithFlags(&s2, cudaStreamNonBlocking) != cudaSuccess) s2 = nullptr;
        if (s2) {
            cudaEventCreateWithFlags(&ev_fork,  cudaEventDisableTiming);
            cudaEventCreateWithFlags(&ev_join,  cudaEventDisableTiming);
            cudaEventCreateWithFlags(&ev_sp1h0, cudaEventDisableTiming);
            cudaEventCreateWithFlags(&ev_g2h0,  cudaEventDisableTiming);
        }
    }

    cudaStream_t cs = s2 ? s2 : (cudaStream_t)0;

    if (s2) {
        cudaEventRecord(ev_fork, 0);
        cudaStreamWaitEvent(s2, ev_fork, 0);
    }

    // --- CSR build on secondary stream (independent of gemm1) ---
    k_zero_deg   <<<(N + 255) / 256, 256, 0, cs>>>(N);
    k_hist       <<<(E + 255) / 256, 256, 0, cs>>>(dst, E);
    k_part_sums  <<<nchunks, 256, 0, cs>>>(N);
    k_scan_chunks<<<nchunks, SCAN_CHUNK, 0, cs>>>(N, E);
    k_scatter    <<<(E + 255) / 256, 256, 0, cs>>>(src, dst, ew, E);
    if (s2) cudaEventRecord(ev_join, s2);

    // --- main stream: W1+W2 fp16 prep + tensor-core gemm1 ---
    k_prep_w<<<(128 * 128 + 255) / 256, 256>>>(W1, W2);
    gemm1_wmma<<<nblk, 256, G1_SMEM_BYTES>>>(x, N);

    if (s2) cudaStreamWaitEvent((cudaStream_t)0, ev_join, 0);

    if (s2) {
        // spmm1 half 0
        spmm1_fused<<<(NH * 32 + 255) / 256, 256>>>(b1, 0, NH);
        cudaEventRecord(ev_sp1h0, 0);
        // gemm2 half 0 on s2, overlapped with spmm1 half 1 on main
        cudaStreamWaitEvent(s2, ev_sp1h0, 0);
        gemm2_wmma<<<nblk_h0, 256, G2_SMEM_BYTES, s2>>>(0, N);
        cudaEventRecord(ev_g2h0, s2);
        // spmm1 half 1 + gemm2 half 1 on main
        spmm1_fused<<<((N - NH) * 32 + 255) / 256, 256>>>(b1, NH, N);
        gemm2_wmma<<<nblk_h1, 256, G2_SMEM_BYTES>>>(NH, N);
        cudaStreamWaitEvent((cudaStream_t)0, ev_g2h0, 0);
    } else {
        spmm1_fused<<<(N * 32 + 255) / 256, 256>>>(b1, 0, N);
        gemm2_wmma<<<nblk, 256, G2_SMEM_BYTES>>>(0, N);
    }

    // out = spmm(A, p) + b2
    spmm2_fused<<<(N * 32 + 255) / 256, 256>>>(b2, out, N);
}